// round 17
// baseline (speedup 1.0000x reference)
#include <cuda_runtime.h>
#include <cstdint>

// ---------------------------------------------------------------------------
// AttentionMapLayer (single fused kernel, one block per batch):
//   out[b,h,w,c] = (t_hat[b,h]*s_hat[b,w] + roi[w]) * ipt[b,h,w,c]
//   s_hat = l2_normalize(s_o, axis=1)  (B,25)
//   t_hat = l2_normalize(t_o, axis=1)  (B,300)
//   roi[w] = 1 for w in {3,8,12,14,17,19}
// B=1024, H=300, W=25, C=16 -> 983 MB HBM stream, HBM-bound.
//
// R16: grid = B. Each block computes ITS batch's norms once (no redundancy,
// barriers only in prologue), caches t_hat[300]/s_hat[25] in smem, then
// streams its 30000 float4 region with the proven ITEMS=4 front-batched
// ldcs/stcs pattern. Eliminates the second kernel + inter-launch gap
// (~10.4us) at the cost of ~1-2us of concurrent prologues.
// ---------------------------------------------------------------------------

#define HEIGHT 300
#define WIDTH  25
#define HW4    ((HEIGHT * WIDTH * 16) / 4)   // 30000 float4 per batch

// roi bitmask over w in [0,25)
#define ROI_MASK ((1u<<3)|(1u<<8)|(1u<<12)|(1u<<14)|(1u<<17)|(1u<<19))

#define ITEMS 4
#define BLKTHREADS 256
#define TILE4 (BLKTHREADS * ITEMS)                 // 1024 float4 per iter
#define NITER ((HW4 + TILE4 - 1) / TILE4)          // 30 (last partial)

__global__ __launch_bounds__(BLKTHREADS)
void fused_attn_kernel(const float*  __restrict__ s_o,
                       const float*  __restrict__ t_o,
                       const float4* __restrict__ ipt,
                       float4*       __restrict__ out)
{
    const int b   = blockIdx.x;
    const int tid = threadIdx.x;

    __shared__ float sm_t[HEIGHT];   // t_hat for this batch
    __shared__ float sm_s[WIDTH];    // s_hat for this batch
    __shared__ float red[8];         // per-warp partial sums (t)
    __shared__ float sm_inv[2];      // {inv_t, inv_s}

    // ---- Prologue: this batch's inverse norms (runs once per block) ----
    float acc_t = 0.0f;
    #pragma unroll
    for (int i = tid; i < HEIGHT; i += BLKTHREADS) {
        float v = t_o[b * HEIGHT + i];
        acc_t += v * v;
    }
    float acc_s = 0.0f;
    if (tid < WIDTH) {
        float v = s_o[b * WIDTH + tid];
        acc_s = v * v;
    }

    #pragma unroll
    for (int off = 16; off > 0; off >>= 1) {
        acc_t += __shfl_down_sync(0xffffffffu, acc_t, off);
        acc_s += __shfl_down_sync(0xffffffffu, acc_s, off);
    }
    const int warp = tid >> 5;
    const int lane = tid & 31;
    if (lane == 0) red[warp] = acc_t;
    __syncthreads();
    if (tid == 0) {
        float sum_t = 0.0f;
        #pragma unroll
        for (int wq = 0; wq < 8; ++wq) sum_t += red[wq];
        sm_inv[0] = rsqrtf(fmaxf(sum_t, 1e-12f));
        sm_inv[1] = rsqrtf(fmaxf(acc_s, 1e-12f));  // warp0 lane0 has full s sum
    }
    __syncthreads();
    const float inv_t = sm_inv[0];
    const float inv_s = sm_inv[1];

    #pragma unroll
    for (int i = tid; i < HEIGHT; i += BLKTHREADS)
        sm_t[i] = t_o[b * HEIGHT + i] * inv_t;     // L1/L2 hit (just read)
    if (tid < WIDTH)
        sm_s[tid] = s_o[b * WIDTH + tid] * inv_s;
    __syncthreads();

    // ---- Main loop: barrier-free stream of this batch's 30000 float4 ----
    const float4* __restrict__ src = ipt + (size_t)b * HW4;
    float4*       __restrict__ dst = out + (size_t)b * HW4;

    for (int it = 0; it < NITER; ++it) {
        const int base = it * TILE4 + tid;

        int  l[ITEMS];
        bool ok[ITEMS];
        #pragma unroll
        for (int j = 0; j < ITEMS; ++j) {
            l[j]  = base + j * BLKTHREADS;
            ok[j] = l[j] < HW4;
        }

        // Phase 1: front-batched independent stream loads, evict-first
        float4 v[ITEMS];
        #pragma unroll
        for (int j = 0; j < ITEMS; ++j)
            if (ok[j]) v[j] = __ldcs(&src[l[j]]);

        // Phase 2: scale from smem (2 LDS + fma per item)
        float sc[ITEMS];
        #pragma unroll
        for (int j = 0; j < ITEMS; ++j) {
            if (ok[j]) {
                const int p = l[j] >> 2;        // local (h,w) index
                const int w = p % WIDTH;
                const int h = p / WIDTH;
                const float roi = ((ROI_MASK >> w) & 1u) ? 1.0f : 0.0f;
                sc[j] = fmaf(sm_t[h], sm_s[w], roi);
            }
        }

        // Phase 3: scale and store (streaming)
        #pragma unroll
        for (int j = 0; j < ITEMS; ++j) {
            if (ok[j]) {
                float4 r = v[j];
                r.x *= sc[j]; r.y *= sc[j]; r.z *= sc[j]; r.w *= sc[j];
                __stcs(&dst[l[j]], r);
            }
        }
    }
}

// ---------------------------------------------------------------------------
// Launch
// ---------------------------------------------------------------------------
extern "C" void kernel_launch(void* const* d_in, const int* in_sizes, int n_in,
                              void* d_out, int out_size)
{
    // Identify inputs by size (robust to metadata ordering):
    //   ipt = B*300*25*16 (largest), t_o = B*300, s_o = B*25
    int ipt_i = 0;
    for (int k = 1; k < n_in; ++k)
        if (in_sizes[k] > in_sizes[ipt_i]) ipt_i = k;
    int a = -1, c = -1;
    for (int k = 0; k < n_in; ++k) {
        if (k == ipt_i) continue;
        if (a < 0) a = k; else c = k;
    }
    int s_i = (in_sizes[a] < in_sizes[c]) ? a : c;
    int t_i = (s_i == a) ? c : a;

    const float* s_o = (const float*)d_in[s_i];
    const float* t_o = (const float*)d_in[t_i];
    const float* ipt = (const float*)d_in[ipt_i];
    float* out = (float*)d_out;

    const int B = in_sizes[t_i] / HEIGHT;   // 1024

    // One block per batch; prologue computes norms, loop streams the region.
    fused_attn_kernel<<<B, BLKTHREADS>>>(
        s_o, t_o, (const float4*)ipt, (float4*)out);
}